// round 5
// baseline (speedup 1.0000x reference)
#include <cuda_runtime.h>
#include <cuda_bf16.h>
#include <cfloat>
#include <cstdint>

// LossFun: loss = -sum over (b,l) of [argmax_v(scores)==target] * w * log(max score) / B
// scores: [B, L, V] float32, targets: [B, L] int32. B=8, L=2048, V=32000.
// picked = max of 32000 uniforms ~ 1-3e-5, so log(picked) is tiny: must use
// accurate logf (not __logf) and a double accumulator to stay under 1e-3.

static constexpr int V_DIM   = 32000;
static constexpr int V_VEC4  = V_DIM / 4;   // 8000
static constexpr double INV_B = 1.0 / 8.0;
static constexpr float  BETA  = 2.0f;

__device__ double g_acc;

__global__ void lossfun_init_kernel() { g_acc = 0.0; }

__global__ __launch_bounds__(256, 8)
void lossfun_argmax_kernel(const float* __restrict__ scores,
                           const int* __restrict__ targets)
{
    const int row = blockIdx.x;
    const float4* __restrict__ p =
        reinterpret_cast<const float4*>(scores + (size_t)row * V_DIM);

    float best = -FLT_MAX;
    int   bidx = 0x7FFFFFFF;

    // Coalesced strided float4 scan; first-index tiebreak on equal values.
    for (int i = threadIdx.x; i < V_VEC4; i += 256) {
        float4 v = __ldg(p + i);
        int base = i << 2;
        if (v.x > best || (v.x == best && base + 0 < bidx)) { best = v.x; bidx = base + 0; }
        if (v.y > best || (v.y == best && base + 1 < bidx)) { best = v.y; bidx = base + 1; }
        if (v.z > best || (v.z == best && base + 2 < bidx)) { best = v.z; bidx = base + 2; }
        if (v.w > best || (v.w == best && base + 3 < bidx)) { best = v.w; bidx = base + 3; }
    }

    // Warp reduce (value-max, lowest index on tie)
    #pragma unroll
    for (int o = 16; o > 0; o >>= 1) {
        float ov = __shfl_down_sync(0xFFFFFFFFu, best, o);
        int   oi = __shfl_down_sync(0xFFFFFFFFu, bidx, o);
        if (ov > best || (ov == best && oi < bidx)) { best = ov; bidx = oi; }
    }

    __shared__ float sv[8];
    __shared__ int   si[8];
    const int lane = threadIdx.x & 31;
    const int wid  = threadIdx.x >> 5;
    if (lane == 0) { sv[wid] = best; si[wid] = bidx; }
    __syncthreads();

    if (threadIdx.x == 0) {
        float fb = sv[0]; int fi = si[0];
        #pragma unroll
        for (int w = 1; w < 8; w++) {
            float ov = sv[w]; int oi = si[w];
            if (ov > fb || (ov == fb && oi < fi)) { fb = ov; fi = oi; }
        }
        int tgt = __ldg(targets + row);
        if (fi == tgt) {
            float w = (tgt == 0) ? 1.0f : BETA;
            // accurate logf: fb is ~1-3e-5, result ~-3e-5; __logf's absolute
            // error near 1 would be ~3e-3 relative here.
            atomicAdd(&g_acc, (double)(-w * logf(fb)));
        }
    }
}

__global__ void lossfun_finalize_kernel(float* __restrict__ out)
{
    out[0] = (float)(g_acc * INV_B);
}

extern "C" void kernel_launch(void* const* d_in, const int* in_sizes, int n_in,
                              void* d_out, int out_size)
{
    const float* scores  = (const float*)d_in[0];
    const int*   targets = (const int*)d_in[1];
    float*       out     = (float*)d_out;

    const int rows = in_sizes[1];   // B * L = 16384

    lossfun_init_kernel<<<1, 1>>>();
    lossfun_argmax_kernel<<<rows, 256>>>(scores, targets);
    lossfun_finalize_kernel<<<1, 1>>>(out);
}